// round 5
// baseline (speedup 1.0000x reference)
#include <cuda_runtime.h>
#include <cstdint>

// Problem constants (shapes fixed by the dataset)
#define DDIM 256
#define BM   128   // rows per block
#define BC   128   // codes per chunk
#define BK   32    // k-tile
#define TM   8     // rows per thread
#define TC   8     // codes per thread (strided by 16 across tx)
#define PAD  33    // smem row stride (floats), conflict-free scalar access
#define MARGIN 0.25f
#define TIE_ULPS 2

__device__ float g_cnorm[1024];
__device__ int   g_list[65536];
__device__ int   g_cnt;

// ---------------------------------------------------------------------------
__global__ void reset_kernel() { g_cnt = 0; }

// ---------------------------------------------------------------------------
// ||c||^2 per code in fp64, rounded to fp32 (correctly rounded).
// ---------------------------------------------------------------------------
__global__ void cnorm_kernel(const float* __restrict__ codes, int C) {
    int warp = (int)((blockIdx.x * blockDim.x + threadIdx.x) >> 5);
    int lane = threadIdx.x & 31;
    if (warp >= C) return;
    const float4* row = (const float4*)(codes + (size_t)warp * DDIM);
    double s = 0.0;
    #pragma unroll
    for (int j = 0; j < 2; j++) {
        float4 v = row[lane + 32 * j];
        s += (double)v.x * v.x + (double)v.y * v.y
           + (double)v.z * v.z + (double)v.w * v.w;
    }
    #pragma unroll
    for (int o = 16; o; o >>= 1) s += __shfl_xor_sync(0xffffffffu, s, o);
    if (lane == 0) g_cnorm[warp] = (float)s;
}

// ---------------------------------------------------------------------------
// Main VQ kernel: per block, 128 rows vs all 1024 codes (8 chunks of 128).
// Tracks top-2 per row; ambiguous rows (gap < MARGIN) go to a worklist.
// ---------------------------------------------------------------------------
extern "C" __global__ void __launch_bounds__(256)
vq_kernel(const float* __restrict__ x, const float* __restrict__ codes,
          float* __restrict__ out, long long out_size, int nrows, int C)
{
    __shared__ float xs[BM][PAD];
    __shared__ float cs[BC][PAD];
    __shared__ float cn_s[1024];
    __shared__ int   bidx_s[BM];

    const int tid = threadIdx.x;
    const int tx  = tid & 15;    // code group
    const int ty  = tid >> 4;    // row group
    const int row_base = blockIdx.x * BM;

    for (int i = tid; i < C; i += 256) cn_s[i] = g_cnorm[i];

    float bestv[TM], best2v[TM];
    int   besti[TM];
    #pragma unroll
    for (int i = 0; i < TM; i++) {
        bestv[i] = 3.4e38f; best2v[i] = 3.4e38f; besti[i] = 0;
    }

    const int lr0 = tid >> 3;        // 0..31
    const int lc4 = (tid & 7) * 4;   // 0,4,...,28

    for (int cc = 0; cc < C; cc += BC) {
        unsigned long long acc2[TM][TC / 2];
        #pragma unroll
        for (int r = 0; r < TM; r++)
            #pragma unroll
            for (int p = 0; p < TC / 2; p++) acc2[r][p] = 0ULL;

        for (int k0 = 0; k0 < DDIM; k0 += BK) {
            #pragma unroll
            for (int j = 0; j < 4; j++) {
                int r = lr0 + 32 * j;
                float4 vx = *(const float4*)&x[(size_t)(row_base + r) * DDIM + k0 + lc4];
                xs[r][lc4 + 0] = vx.x; xs[r][lc4 + 1] = vx.y;
                xs[r][lc4 + 2] = vx.z; xs[r][lc4 + 3] = vx.w;
                float4 vc = *(const float4*)&codes[(size_t)(cc + r) * DDIM + k0 + lc4];
                cs[r][lc4 + 0] = vc.x; cs[r][lc4 + 1] = vc.y;
                cs[r][lc4 + 2] = vc.z; cs[r][lc4 + 3] = vc.w;
            }
            __syncthreads();

            #pragma unroll 8
            for (int kk = 0; kk < BK; kk++) {
                float a[TM], b[TC];
                #pragma unroll
                for (int i = 0; i < TM; i++) a[i] = xs[ty * TM + i][kk];
                #pragma unroll
                for (int i = 0; i < TC; i++) b[i] = cs[tx + 16 * i][kk];

                unsigned long long b2[TC / 2];
                #pragma unroll
                for (int p = 0; p < TC / 2; p++)
                    asm("mov.b64 %0, {%1, %2};" : "=l"(b2[p])
                        : "f"(b[2 * p]), "f"(b[2 * p + 1]));

                #pragma unroll
                for (int r = 0; r < TM; r++) {
                    unsigned long long a2;
                    asm("mov.b64 %0, {%1, %1};" : "=l"(a2) : "f"(a[r]));
                    #pragma unroll
                    for (int p = 0; p < TC / 2; p++)
                        asm("fma.rn.f32x2 %0, %1, %2, %0;"
                            : "+l"(acc2[r][p]) : "l"(a2), "l"(b2[p]));
                }
            }
            __syncthreads();
        }

        // per-chunk top-2 update: score = ||c||^2 - 2*dot (row-constant dropped)
        #pragma unroll
        for (int r = 0; r < TM; r++) {
            #pragma unroll
            for (int p = 0; p < TC / 2; p++) {
                float lo = __uint_as_float((unsigned)(acc2[r][p] & 0xffffffffULL));
                float hi = __uint_as_float((unsigned)(acc2[r][p] >> 32));
                int clo = cc + tx + 32 * p;
                int chi = clo + 16;
                float slo = cn_s[clo] - 2.0f * lo;
                float shi = cn_s[chi] - 2.0f * hi;
                if (slo < bestv[r]) {
                    best2v[r] = bestv[r]; bestv[r] = slo; besti[r] = clo;
                } else {
                    if (slo == bestv[r] && clo < besti[r]) besti[r] = clo;
                    best2v[r] = fminf(best2v[r], slo);
                }
                if (shi < bestv[r]) {
                    best2v[r] = bestv[r]; bestv[r] = shi; besti[r] = chi;
                } else {
                    if (shi == bestv[r] && chi < besti[r]) besti[r] = chi;
                    best2v[r] = fminf(best2v[r], shi);
                }
            }
        }
    }

    // --- cross-thread (tx) top-2 merge across 16 code groups ---
    __syncthreads();  // done with xs/cs; reuse as scratch
    float* rv  = &xs[0][0];                       // [128][16] floats (8KB)
    int*   ri  = (int*)(&xs[0][0]) + 2048;        // [128][16] ints   (8KB)
    float* rv2 = &cs[0][0];                       // [128][16] floats (8KB)
    #pragma unroll
    for (int i = 0; i < TM; i++) {
        int r = ty * TM + i;
        rv [r * 16 + tx] = bestv[i];
        ri [r * 16 + tx] = besti[i];
        rv2[r * 16 + tx] = best2v[i];
    }
    __syncthreads();

    const long long NQ = (long long)nrows * DDIM;
    if (tid < BM) {
        float b1 = rv[tid * 16], b2f = rv2[tid * 16];
        int   i1 = ri[tid * 16];
        #pragma unroll
        for (int j = 1; j < 16; j++) {
            float v  = rv [tid * 16 + j];
            int   ii = ri [tid * 16 + j];
            float v2 = rv2[tid * 16 + j];
            if (v < b1) {
                b2f = fminf(b1, v2); b1 = v; i1 = ii;
            } else {
                if (v == b1 && ii < i1) i1 = ii;
                b2f = fminf(b2f, fminf(v, v2));
            }
        }
        bidx_s[tid] = i1;
        long long row = row_base + tid;
        if (b2f - b1 < MARGIN) {
            int slot = atomicAdd(&g_cnt, 1);
            g_list[slot] = (int)row;
        }
        if (out_size >= NQ + nrows) {
            out[NQ + row] = (float)i1;
        } else if (out_size < NQ) {
            if (row < out_size) out[row] = (float)i1;
        }
    }
    __syncthreads();

    // --- gather quantized = codes[best] ---
    if (out_size >= NQ) {
        const float4* c4 = (const float4*)codes;
        float4* o4 = (float4*)out;
        for (int i = tid; i < BM * (DDIM / 4); i += 256) {
            int r = i >> 6;
            int q = i & 63;
            o4[(size_t)(row_base + r) * (DDIM / 4) + q] =
                c4[(size_t)bidx_s[r] * (DDIM / 4) + q];
        }
    }
}

// ---------------------------------------------------------------------------
// Refine kernel: for ambiguous rows:
//   d32(c) = fp32( fp32(s1_32 - 2*dot_32) + cn_32 )  with correctly-rounded
//            s1_32, dot_32, cn_32 (fp64 accumulation -> fp32).
//   Selection: vm = min_c d32(c); winner = SMALLEST index c with
//              d32(c) <= vm + TIE_ULPS ulps.
// Rationale: a sub-ulp true gap makes the reference's two fp32 distances
// exactly equal, and jnp.argmin then returns the lower index. The ulp window
// replicates that deterministically despite +-1 ulp discrepancies between my
// rounding and XLA's.
// ---------------------------------------------------------------------------
__global__ void __launch_bounds__(256)
refine_kernel(const float* __restrict__ x, const float* __restrict__ codes,
              float* __restrict__ out, long long NQ, long long out_size,
              int nrows, int C)
{
    __shared__ float  xr[DDIM];
    __shared__ double partial[256];
    __shared__ float  fv[256];
    __shared__ int    fi[256];
    __shared__ int    sel;
    __shared__ float  vm_s;

    int t = threadIdx.x;
    int cnt = g_cnt;
    if (cnt > 65536) cnt = 65536;

    for (int w = blockIdx.x; w < cnt; w += gridDim.x) {
        int row = g_list[w];
        xr[t] = x[(size_t)row * DDIM + t];
        __syncthreads();

        // s1 = ||x||^2: correctly rounded fp32
        partial[t] = (double)xr[t] * (double)xr[t];
        __syncthreads();
        for (int s = 128; s; s >>= 1) {
            if (t < s) partial[t] += partial[t + s];
            __syncthreads();
        }
        float s1f = (float)partial[0];

        // each thread: 4 codes (t, t+256, t+512, t+768); keep d32 values
        float dv[4];
        #pragma unroll
        for (int c4i = 0; c4i < 4; c4i++) {
            int c = t + 256 * c4i;
            dv[c4i] = 3.4e38f;
            if (c < C) {
                const float* crow = codes + (size_t)c * DDIM;
                double dot = 0.0;
                #pragma unroll 8
                for (int k = 0; k < DDIM; k++)
                    dot = fma((double)xr[k], (double)__ldg(&crow[k]), dot);
                float dotf = (float)dot;            // correctly rounded
                float t1   = s1f - 2.0f * dotf;     // fp32 round
                dv[c4i]    = t1 + g_cnorm[c];       // fp32 round
            }
        }

        // phase 1: global min value
        float bv = fminf(fminf(dv[0], dv[1]), fminf(dv[2], dv[3]));
        fv[t] = bv;
        __syncthreads();
        for (int s = 128; s; s >>= 1) {
            if (t < s) fv[t] = fminf(fv[t], fv[t + s]);
            __syncthreads();
        }
        if (t == 0) vm_s = fv[0];
        __syncthreads();
        float vm = vm_s;
        // tie window: vm bumped by TIE_ULPS ulps (d values are positive)
        float tie_hi = __int_as_float(__float_as_int(vm) + TIE_ULPS);

        // phase 2: smallest index within the tie window
        int bi = 0x7fffffff;
        #pragma unroll
        for (int c4i = 0; c4i < 4; c4i++) {
            int c = t + 256 * c4i;
            if (c < C && dv[c4i] <= tie_hi && c < bi) bi = c;
        }
        fi[t] = bi;
        __syncthreads();
        for (int s = 128; s; s >>= 1) {
            if (t < s) fi[t] = min(fi[t], fi[t + s]);
            __syncthreads();
        }
        if (t == 0) {
            sel = fi[0];
            if (out_size >= NQ + nrows) out[NQ + row] = (float)fi[0];
            else if (out_size < NQ && row < out_size) out[row] = (float)fi[0];
        }
        __syncthreads();

        // rewrite gathered row
        if (out_size >= NQ)
            out[(size_t)row * DDIM + t] = codes[(size_t)sel * DDIM + t];
        __syncthreads();
    }
}

// ---------------------------------------------------------------------------
extern "C" void kernel_launch(void* const* d_in, const int* in_sizes, int n_in,
                              void* d_out, int out_size)
{
    const float* x     = (const float*)d_in[0];
    const float* codes = (const float*)d_in[1];
    int nrows = in_sizes[0] / DDIM;   // 65536
    int C     = in_sizes[1] / DDIM;   // 1024

    reset_kernel<<<1, 1>>>();

    int threads = 256;
    int blocks = (C * 32 + threads - 1) / threads;
    cnorm_kernel<<<blocks, threads>>>(codes, C);

    dim3 grid(nrows / BM);
    vq_kernel<<<grid, 256>>>(x, codes, (float*)d_out, (long long)out_size,
                             nrows, C);

    long long NQ = (long long)nrows * DDIM;
    refine_kernel<<<1024, 256>>>(x, codes, (float*)d_out, NQ,
                                 (long long)out_size, nrows, C);
}

// round 7
// speedup vs baseline: 3.4946x; 3.4946x over previous
#include <cuda_runtime.h>
#include <cuda_bf16.h>
#include <cstdint>

// Problem constants (fixed by dataset)
#define DDIM 256
#define CODES 1024
#define BM   128          // rows per CTA
#define BN   128          // codes per chunk
#define NCHUNK 8
#define MARGIN 0.05f
#define TIE_ULPS 2

// dynamic smem layout (bytes)
#define SM_CN     0          // 1024 f32          (4096)
#define SM_BIDX   4096       // 128 int           (512)
#define SM_A_H    8192       // 128 rows x 528B   (67584)
#define SM_A_L    75776      // 128 rows x 528B   (67584)
#define SM_B      143360     // 2 stages x 2 mats x 128 x 144B (73728)
#define SM_TOTAL  217088
#define A_STRIDE  528        // 256 bf16 + 8 pad elems
#define B_STRIDE  144        // 64 bf16 + 8 pad elems
#define B_MAT     18432      // 128 * 144
#define B_STAGE   36864      // 2 matrices

__device__ float                          g_cnorm[1024];
__device__ __align__(256) __nv_bfloat16   g_ch[1024 * 256];
__device__ __align__(256) __nv_bfloat16   g_cl[1024 * 256];
__device__ int                            g_list[65536];
__device__ int                            g_cnt;

// ---------------------------------------------------------------------------
__device__ __forceinline__ uint32_t smem_to_u32(const void* p) {
    uint32_t a;
    asm("{ .reg .u64 t; cvta.to.shared.u64 t, %1; cvt.u32.u64 %0, t; }"
        : "=r"(a) : "l"(p));
    return a;
}
__device__ __forceinline__ void cp16(uint32_t dst, const void* src) {
    asm volatile("cp.async.cg.shared.global [%0], [%1], 16;"
                 :: "r"(dst), "l"(src));
}
#define CP_COMMIT() asm volatile("cp.async.commit_group;" ::: "memory")
#define CP_WAIT(n)  asm volatile("cp.async.wait_group %0;" :: "n"(n) : "memory")

__device__ __forceinline__ void ldsm4(uint32_t* r, uint32_t addr) {
    asm volatile("ldmatrix.sync.aligned.m8n8.x4.shared.b16 {%0,%1,%2,%3}, [%4];"
                 : "=r"(r[0]), "=r"(r[1]), "=r"(r[2]), "=r"(r[3]) : "r"(addr));
}
__device__ __forceinline__ void mma_bf16(float* d, const uint32_t* a,
                                         const uint32_t* b) {
    asm volatile(
        "mma.sync.aligned.m16n8k16.row.col.f32.bf16.bf16.f32 "
        "{%0,%1,%2,%3}, {%4,%5,%6,%7}, {%8,%9}, {%0,%1,%2,%3};"
        : "+f"(d[0]), "+f"(d[1]), "+f"(d[2]), "+f"(d[3])
        : "r"(a[0]), "r"(a[1]), "r"(a[2]), "r"(a[3]), "r"(b[0]), "r"(b[1]));
}

// ---------------------------------------------------------------------------
__global__ void reset_kernel() { g_cnt = 0; }

// ||c||^2 per code in fp64 -> fp32 (correctly rounded)
__global__ void cnorm_kernel(const float* __restrict__ codes, int C) {
    int warp = (int)((blockIdx.x * blockDim.x + threadIdx.x) >> 5);
    int lane = threadIdx.x & 31;
    if (warp >= C) return;
    const float4* row = (const float4*)(codes + (size_t)warp * DDIM);
    double s = 0.0;
    #pragma unroll
    for (int j = 0; j < 2; j++) {
        float4 v = row[lane + 32 * j];
        s += (double)v.x * v.x + (double)v.y * v.y
           + (double)v.z * v.z + (double)v.w * v.w;
    }
    #pragma unroll
    for (int o = 16; o; o >>= 1) s += __shfl_xor_sync(0xffffffffu, s, o);
    if (lane == 0) g_cnorm[warp] = (float)s;
}

// codes -> bf16 hi/lo split
__global__ void prep_codes(const float* __restrict__ codes) {
    int c = blockIdx.x;
    int t = threadIdx.x;
    float v = codes[(size_t)c * DDIM + t];
    __nv_bfloat16 h = __float2bfloat16_rn(v);
    float lo = v - __bfloat162float(h);
    g_ch[(size_t)c * DDIM + t] = h;
    g_cl[(size_t)c * DDIM + t] = __float2bfloat16_rn(lo);
}

// ---------------------------------------------------------------------------
// HMMA ranking kernel: dot = xh.ch + xh.cl + xl.ch (bf16 in, fp32 acc)
// ---------------------------------------------------------------------------
__global__ void __launch_bounds__(256, 1)
vq_mma(const float* __restrict__ x, const float* __restrict__ codes,
       float* __restrict__ out, long long out_size, int nrows)
{
    extern __shared__ char smem[];
    const uint32_t sb   = smem_to_u32(smem);
    const int tid  = threadIdx.x;
    const int wid  = tid >> 5;
    const int lane = tid & 31;
    const int wm   = wid & 1;          // m band: rows wm*64
    const int wn   = wid >> 1;         // n band: cols wn*32
    const int row_base = blockIdx.x * BM;

    float* cn_s   = (float*)(smem + SM_CN);
    int*   bidx_s = (int*)(smem + SM_BIDX);

    for (int i = tid; i < CODES; i += 256) cn_s[i] = g_cnorm[i];

    // --- convert x rows to bf16 hi/lo in smem (row-major, padded stride) ---
    const float4* x4 = (const float4*)x + (size_t)row_base * (DDIM / 4);
    for (int idx = tid; idx < BM * (DDIM / 4); idx += 256) {
        float4 v = x4[idx];
        int r  = idx >> 6;
        int kq = idx & 63;                    // float4 index
        __nv_bfloat16 h0 = __float2bfloat16_rn(v.x);
        __nv_bfloat16 h1 = __float2bfloat16_rn(v.y);
        __nv_bfloat16 h2 = __float2bfloat16_rn(v.z);
        __nv_bfloat16 h3 = __float2bfloat16_rn(v.w);
        __nv_bfloat16 l0 = __float2bfloat16_rn(v.x - __bfloat162float(h0));
        __nv_bfloat16 l1 = __float2bfloat16_rn(v.y - __bfloat162float(h1));
        __nv_bfloat16 l2 = __float2bfloat16_rn(v.z - __bfloat162float(h2));
        __nv_bfloat16 l3 = __float2bfloat16_rn(v.w - __bfloat162float(h3));
        uint32_t h01 = ((uint32_t)__bfloat16_as_ushort(h1) << 16) | __bfloat16_as_ushort(h0);
        uint32_t h23 = ((uint32_t)__bfloat16_as_ushort(h3) << 16) | __bfloat16_as_ushort(h2);
        uint32_t l01 = ((uint32_t)__bfloat16_as_ushort(l1) << 16) | __bfloat16_as_ushort(l0);
        uint32_t l23 = ((uint32_t)__bfloat16_as_ushort(l3) << 16) | __bfloat16_as_ushort(l2);
        int off = r * A_STRIDE + kq * 8;
        *(uint32_t*)(smem + SM_A_H + off)     = h01;
        *(uint32_t*)(smem + SM_A_H + off + 4) = h23;
        *(uint32_t*)(smem + SM_A_L + off)     = l01;
        *(uint32_t*)(smem + SM_A_L + off + 4) = l23;
    }
    __syncthreads();

    // running per-lane top-2: 8 row slots (mt*2 + hi)
    float bv[8], b2[8];
    int   bi[8];
    #pragma unroll
    for (int i = 0; i < 8; i++) { bv[i] = 3.4e38f; b2[i] = 3.4e38f; bi[i] = 0; }

    for (int chunk = 0; chunk < NCHUNK; chunk++) {
        float acc[4][4][4];
        #pragma unroll
        for (int m = 0; m < 4; m++)
            #pragma unroll
            for (int n = 0; n < 4; n++)
                #pragma unroll
                for (int q = 0; q < 4; q++) acc[m][n][q] = 0.0f;

        // stage-0 async load
        {
            #pragma unroll
            for (int i = 0; i < 8; i++) {
                int linear = tid + i * 256;
                int mat = linear >> 10, rr = (linear >> 3) & 127, seg = linear & 7;
                uint32_t dst = sb + SM_B + mat * B_MAT + rr * B_STRIDE + seg * 16;
                const __nv_bfloat16* src = (mat ? g_cl : g_ch)
                    + ((size_t)(chunk * BN + rr) * DDIM + seg * 8);
                cp16(dst, src);
            }
            CP_COMMIT();
        }

        for (int ks = 0; ks < 4; ks++) {
            if (ks < 3) {
                int nb = (ks + 1) & 1;
                #pragma unroll
                for (int i = 0; i < 8; i++) {
                    int linear = tid + i * 256;
                    int mat = linear >> 10, rr = (linear >> 3) & 127, seg = linear & 7;
                    uint32_t dst = sb + SM_B + nb * B_STAGE + mat * B_MAT
                                 + rr * B_STRIDE + seg * 16;
                    const __nv_bfloat16* src = (mat ? g_cl : g_ch)
                        + ((size_t)(chunk * BN + rr) * DDIM + (ks + 1) * 64 + seg * 8);
                    cp16(dst, src);
                }
                CP_COMMIT();
                CP_WAIT(1);
            } else {
                CP_WAIT(0);
            }
            __syncthreads();

            const uint32_t bbase = sb + SM_B + (ks & 1) * B_STAGE;
            #pragma unroll
            for (int k16 = 0; k16 < 4; k16++) {
                int kel = k16 * 16;
                uint32_t ah[4][4], al[4][4];
                #pragma unroll
                for (int mt = 0; mt < 4; mt++) {
                    uint32_t ar = sb + SM_A_H
                        + (wm * 64 + mt * 16 + (lane & 15)) * A_STRIDE
                        + (ks * 64 + kel + (lane >> 4) * 8) * 2;
                    ldsm4(ah[mt], ar);
                    ldsm4(al[mt], ar + (SM_A_L - SM_A_H));
                }
                #pragma unroll
                for (int np = 0; np < 2; np++) {
                    uint32_t bh[4], bl[4];
                    uint32_t br = bbase
                        + (wn * 32 + np * 16 + (lane & 7) + (lane >> 4) * 8) * B_STRIDE
                        + (kel + ((lane >> 3) & 1) * 8) * 2;
                    ldsm4(bh, br);
                    ldsm4(bl, br + B_MAT);
                    #pragma unroll
                    for (int mt = 0; mt < 4; mt++) {
                        mma_bf16(acc[mt][np * 2 + 0], ah[mt], bh + 0);
                        mma_bf16(acc[mt][np * 2 + 1], ah[mt], bh + 2);
                        mma_bf16(acc[mt][np * 2 + 0], ah[mt], bl + 0);
                        mma_bf16(acc[mt][np * 2 + 1], ah[mt], bl + 2);
                        mma_bf16(acc[mt][np * 2 + 0], al[mt], bh + 0);
                        mma_bf16(acc[mt][np * 2 + 1], al[mt], bh + 2);
                    }
                }
            }
            __syncthreads();
        }

        // --- chunk epilogue: scores + per-lane top-2 update ---
        #pragma unroll
        for (int mt = 0; mt < 4; mt++) {
            #pragma unroll
            for (int nt = 0; nt < 4; nt++) {
                int col = chunk * BN + wn * 32 + nt * 8 + (lane & 3) * 2;
                float s0 = cn_s[col]     - 2.0f * acc[mt][nt][0];
                float s1 = cn_s[col + 1] - 2.0f * acc[mt][nt][1];
                float s2 = cn_s[col]     - 2.0f * acc[mt][nt][2];
                float s3 = cn_s[col + 1] - 2.0f * acc[mt][nt][3];
                int sl0 = mt * 2, sl1 = mt * 2 + 1;
                if (s0 < bv[sl0]) { b2[sl0] = bv[sl0]; bv[sl0] = s0; bi[sl0] = col; }
                else b2[sl0] = fminf(b2[sl0], s0);
                if (s1 < bv[sl0]) { b2[sl0] = bv[sl0]; bv[sl0] = s1; bi[sl0] = col + 1; }
                else b2[sl0] = fminf(b2[sl0], s1);
                if (s2 < bv[sl1]) { b2[sl1] = bv[sl1]; bv[sl1] = s2; bi[sl1] = col; }
                else b2[sl1] = fminf(b2[sl1], s2);
                if (s3 < bv[sl1]) { b2[sl1] = bv[sl1]; bv[sl1] = s3; bi[sl1] = col + 1; }
                else b2[sl1] = fminf(b2[sl1], s3);
            }
        }
    }

    // --- cross-lane (quad) top-2 merge per row slot ---
    #pragma unroll
    for (int s = 0; s < 8; s++) {
        #pragma unroll
        for (int off = 1; off <= 2; off <<= 1) {
            float ov = __shfl_xor_sync(0xffffffffu, bv[s], off);
            float o2 = __shfl_xor_sync(0xffffffffu, b2[s], off);
            int   oi = __shfl_xor_sync(0xffffffffu, bi[s], off);
            float n2 = fminf(fminf(b2[s], o2), fmaxf(bv[s], ov));
            if (ov < bv[s] || (ov == bv[s] && oi < bi[s])) { bv[s] = ov; bi[s] = oi; }
            b2[s] = n2;
        }
    }
    __syncthreads();   // done with B buffers; reuse as merge scratch

    float* V1 = (float*)(smem + SM_B);            // [128][4]
    float* V2 = (float*)(smem + SM_B + 2048);
    int*   I1 = (int*)(smem + SM_B + 4096);
    if ((lane & 3) == 0) {
        #pragma unroll
        for (int s = 0; s < 8; s++) {
            int mt = s >> 1, hi = s & 1;
            int r = wm * 64 + mt * 16 + (lane >> 2) + hi * 8;
            V1[r * 4 + wn] = bv[s];
            V2[r * 4 + wn] = b2[s];
            I1[r * 4 + wn] = bi[s];
        }
    }
    __syncthreads();

    const long long NQ = (long long)nrows * DDIM;
    if (tid < BM) {
        float v1 = V1[tid * 4], v2 = V2[tid * 4];
        int   i1 = I1[tid * 4];
        #pragma unroll
        for (int j = 1; j < 4; j++) {
            float a1 = V1[tid * 4 + j], a2 = V2[tid * 4 + j];
            int   ai = I1[tid * 4 + j];
            float n2 = fminf(fminf(v2, a2), fmaxf(v1, a1));
            if (a1 < v1 || (a1 == v1 && ai < i1)) { v1 = a1; i1 = ai; }
            v2 = n2;
        }
        bidx_s[tid] = i1;
        long long row = row_base + tid;
        if (v2 - v1 < MARGIN) {
            int slot = atomicAdd(&g_cnt, 1);
            g_list[slot] = (int)row;
        }
        if (out_size >= NQ + nrows) out[NQ + row] = (float)i1;
        else if (out_size < NQ && row < out_size) out[row] = (float)i1;
    }
    __syncthreads();

    // --- gather quantized = codes[best] ---
    if (out_size >= NQ) {
        const float4* c4 = (const float4*)codes;
        float4* o4 = (float4*)out;
        for (int i = tid; i < BM * (DDIM / 4); i += 256) {
            int r = i >> 6;
            int q = i & 63;
            o4[(size_t)(row_base + r) * (DDIM / 4) + q] =
                c4[(size_t)bidx_s[r] * (DDIM / 4) + q];
        }
    }
}

// ---------------------------------------------------------------------------
// Refine kernel (identical to R5 pass): exact re-decision with tie window.
// ---------------------------------------------------------------------------
__global__ void __launch_bounds__(256)
refine_kernel(const float* __restrict__ x, const float* __restrict__ codes,
              float* __restrict__ out, long long NQ, long long out_size,
              int nrows, int C)
{
    __shared__ float  xr[DDIM];
    __shared__ double partial[256];
    __shared__ float  fv[256];
    __shared__ int    fi[256];
    __shared__ int    sel;
    __shared__ float  vm_s;

    int t = threadIdx.x;
    int cnt = g_cnt;
    if (cnt > 65536) cnt = 65536;

    for (int w = blockIdx.x; w < cnt; w += gridDim.x) {
        int row = g_list[w];
        xr[t] = x[(size_t)row * DDIM + t];
        __syncthreads();

        partial[t] = (double)xr[t] * (double)xr[t];
        __syncthreads();
        for (int s = 128; s; s >>= 1) {
            if (t < s) partial[t] += partial[t + s];
            __syncthreads();
        }
        float s1f = (float)partial[0];

        float dv[4];
        #pragma unroll
        for (int c4i = 0; c4i < 4; c4i++) {
            int c = t + 256 * c4i;
            dv[c4i] = 3.4e38f;
            if (c < C) {
                const float* crow = codes + (size_t)c * DDIM;
                double dot = 0.0;
                #pragma unroll 8
                for (int k = 0; k < DDIM; k++)
                    dot = fma((double)xr[k], (double)__ldg(&crow[k]), dot);
                float dotf = (float)dot;
                float t1   = s1f - 2.0f * dotf;
                dv[c4i]    = t1 + g_cnorm[c];
            }
        }

        float bvv = fminf(fminf(dv[0], dv[1]), fminf(dv[2], dv[3]));
        fv[t] = bvv;
        __syncthreads();
        for (int s = 128; s; s >>= 1) {
            if (t < s) fv[t] = fminf(fv[t], fv[t + s]);
            __syncthreads();
        }
        if (t == 0) vm_s = fv[0];
        __syncthreads();
        float vm = vm_s;
        float tie_hi = __int_as_float(__float_as_int(vm) + TIE_ULPS);

        int bii = 0x7fffffff;
        #pragma unroll
        for (int c4i = 0; c4i < 4; c4i++) {
            int c = t + 256 * c4i;
            if (c < C && dv[c4i] <= tie_hi && c < bii) bii = c;
        }
        fi[t] = bii;
        __syncthreads();
        for (int s = 128; s; s >>= 1) {
            if (t < s) fi[t] = min(fi[t], fi[t + s]);
            __syncthreads();
        }
        if (t == 0) {
            sel = fi[0];
            if (out_size >= NQ + nrows) out[NQ + row] = (float)fi[0];
            else if (out_size < NQ && row < out_size) out[row] = (float)fi[0];
        }
        __syncthreads();

        if (out_size >= NQ)
            out[(size_t)row * DDIM + t] = codes[(size_t)sel * DDIM + t];
        __syncthreads();
    }
}

// ---------------------------------------------------------------------------
extern "C" void kernel_launch(void* const* d_in, const int* in_sizes, int n_in,
                              void* d_out, int out_size)
{
    const float* x     = (const float*)d_in[0];
    const float* codes = (const float*)d_in[1];
    int nrows = in_sizes[0] / DDIM;   // 65536
    int C     = in_sizes[1] / DDIM;   // 1024

    cudaFuncSetAttribute(vq_mma, cudaFuncAttributeMaxDynamicSharedMemorySize,
                         SM_TOTAL);

    reset_kernel<<<1, 1>>>();
    cnorm_kernel<<<(C * 32 + 255) / 256, 256>>>(codes, C);
    prep_codes<<<C, 256>>>(codes);

    vq_mma<<<nrows / BM, 256, SM_TOTAL>>>(x, codes, (float*)d_out,
                                          (long long)out_size, nrows);

    long long NQ = (long long)nrows * DDIM;
    refine_kernel<<<1024, 256>>>(x, codes, (float*)d_out, NQ,
                                 (long long)out_size, nrows, C);
}

// round 8
// speedup vs baseline: 5.4115x; 1.5485x over previous
#include <cuda_runtime.h>
#include <cuda_bf16.h>
#include <cstdint>

// Problem constants (fixed by dataset)
#define DDIM 256
#define CODES 1024
#define BM   128          // rows per CTA
#define BN   128          // codes per chunk
#define NCHUNK 8
#define MARGIN 0.02f
#define TIE_ULPS 2
#define FILT_EPS 4e-3f

// dynamic smem layout (bytes)
#define SM_CN     0          // 1024 f32          (4096)
#define SM_BIDX   4096       // 128 int           (512)
#define SM_A_H    8192       // 128 rows x 528B   (67584)
#define SM_A_L    75776      // 128 rows x 528B   (67584)
#define SM_B      143360     // 2 stages x 2 mats x 128 x 144B (73728)
#define SM_TOTAL  217088
#define A_STRIDE  528        // 256 bf16 + 8 pad elems
#define B_STRIDE  144        // 64 bf16 + 8 pad elems
#define B_MAT     18432      // 128 * 144
#define B_STAGE   36864      // 2 matrices

__device__ float                          g_cnorm[1024];
__device__ __align__(256) __nv_bfloat16   g_ch[1024 * 256];
__device__ __align__(256) __nv_bfloat16   g_cl[1024 * 256];
__device__ int                            g_list[65536];
__device__ int                            g_cnt;

// ---------------------------------------------------------------------------
__device__ __forceinline__ uint32_t smem_to_u32(const void* p) {
    uint32_t a;
    asm("{ .reg .u64 t; cvta.to.shared.u64 t, %1; cvt.u32.u64 %0, t; }"
        : "=r"(a) : "l"(p));
    return a;
}
__device__ __forceinline__ void cp16(uint32_t dst, const void* src) {
    asm volatile("cp.async.cg.shared.global [%0], [%1], 16;"
                 :: "r"(dst), "l"(src));
}
#define CP_COMMIT() asm volatile("cp.async.commit_group;" ::: "memory")
#define CP_WAIT(n)  asm volatile("cp.async.wait_group %0;" :: "n"(n) : "memory")

__device__ __forceinline__ void ldsm4(uint32_t* r, uint32_t addr) {
    asm volatile("ldmatrix.sync.aligned.m8n8.x4.shared.b16 {%0,%1,%2,%3}, [%4];"
                 : "=r"(r[0]), "=r"(r[1]), "=r"(r[2]), "=r"(r[3]) : "r"(addr));
}
__device__ __forceinline__ void mma_bf16(float* d, const uint32_t* a,
                                         const uint32_t* b) {
    asm volatile(
        "mma.sync.aligned.m16n8k16.row.col.f32.bf16.bf16.f32 "
        "{%0,%1,%2,%3}, {%4,%5,%6,%7}, {%8,%9}, {%0,%1,%2,%3};"
        : "+f"(d[0]), "+f"(d[1]), "+f"(d[2]), "+f"(d[3])
        : "r"(a[0]), "r"(a[1]), "r"(a[2]), "r"(a[3]), "r"(b[0]), "r"(b[1]));
}

// ---------------------------------------------------------------------------
__global__ void reset_kernel() { g_cnt = 0; }

// Merged prep: per code row -> bf16 hi/lo split + ||c||^2 (fp64 -> fp32).
// One block per code (256 threads).
__global__ void prep_codes(const float* __restrict__ codes) {
    __shared__ double partial[256];
    int c = blockIdx.x;
    int t = threadIdx.x;
    float v = codes[(size_t)c * DDIM + t];
    __nv_bfloat16 h = __float2bfloat16_rn(v);
    float lo = v - __bfloat162float(h);
    g_ch[(size_t)c * DDIM + t] = h;
    g_cl[(size_t)c * DDIM + t] = __float2bfloat16_rn(lo);
    partial[t] = (double)v * (double)v;
    __syncthreads();
    for (int s = 128; s; s >>= 1) {
        if (t < s) partial[t] += partial[t + s];
        __syncthreads();
    }
    if (t == 0) g_cnorm[c] = (float)partial[0];
}

// ---------------------------------------------------------------------------
// HMMA ranking kernel: dot = xh.ch + xh.cl + xl.ch (bf16 in, fp32 acc)
// (mainloop identical to R7 pass; only MARGIN changed)
// ---------------------------------------------------------------------------
__global__ void __launch_bounds__(256, 1)
vq_mma(const float* __restrict__ x, const float* __restrict__ codes,
       float* __restrict__ out, long long out_size, int nrows)
{
    extern __shared__ char smem[];
    const uint32_t sb   = smem_to_u32(smem);
    const int tid  = threadIdx.x;
    const int wid  = tid >> 5;
    const int lane = tid & 31;
    const int wm   = wid & 1;
    const int wn   = wid >> 1;
    const int row_base = blockIdx.x * BM;

    float* cn_s   = (float*)(smem + SM_CN);
    int*   bidx_s = (int*)(smem + SM_BIDX);

    for (int i = tid; i < CODES; i += 256) cn_s[i] = g_cnorm[i];

    const float4* x4 = (const float4*)x + (size_t)row_base * (DDIM / 4);
    for (int idx = tid; idx < BM * (DDIM / 4); idx += 256) {
        float4 v = x4[idx];
        int r  = idx >> 6;
        int kq = idx & 63;
        __nv_bfloat16 h0 = __float2bfloat16_rn(v.x);
        __nv_bfloat16 h1 = __float2bfloat16_rn(v.y);
        __nv_bfloat16 h2 = __float2bfloat16_rn(v.z);
        __nv_bfloat16 h3 = __float2bfloat16_rn(v.w);
        __nv_bfloat16 l0 = __float2bfloat16_rn(v.x - __bfloat162float(h0));
        __nv_bfloat16 l1 = __float2bfloat16_rn(v.y - __bfloat162float(h1));
        __nv_bfloat16 l2 = __float2bfloat16_rn(v.z - __bfloat162float(h2));
        __nv_bfloat16 l3 = __float2bfloat16_rn(v.w - __bfloat162float(h3));
        uint32_t h01 = ((uint32_t)__bfloat16_as_ushort(h1) << 16) | __bfloat16_as_ushort(h0);
        uint32_t h23 = ((uint32_t)__bfloat16_as_ushort(h3) << 16) | __bfloat16_as_ushort(h2);
        uint32_t l01 = ((uint32_t)__bfloat16_as_ushort(l1) << 16) | __bfloat16_as_ushort(l0);
        uint32_t l23 = ((uint32_t)__bfloat16_as_ushort(l3) << 16) | __bfloat16_as_ushort(l2);
        int off = r * A_STRIDE + kq * 8;
        *(uint32_t*)(smem + SM_A_H + off)     = h01;
        *(uint32_t*)(smem + SM_A_H + off + 4) = h23;
        *(uint32_t*)(smem + SM_A_L + off)     = l01;
        *(uint32_t*)(smem + SM_A_L + off + 4) = l23;
    }
    __syncthreads();

    float bv[8], b2[8];
    int   bi[8];
    #pragma unroll
    for (int i = 0; i < 8; i++) { bv[i] = 3.4e38f; b2[i] = 3.4e38f; bi[i] = 0; }

    for (int chunk = 0; chunk < NCHUNK; chunk++) {
        float acc[4][4][4];
        #pragma unroll
        for (int m = 0; m < 4; m++)
            #pragma unroll
            for (int n = 0; n < 4; n++)
                #pragma unroll
                for (int q = 0; q < 4; q++) acc[m][n][q] = 0.0f;

        {
            #pragma unroll
            for (int i = 0; i < 8; i++) {
                int linear = tid + i * 256;
                int mat = linear >> 10, rr = (linear >> 3) & 127, seg = linear & 7;
                uint32_t dst = sb + SM_B + mat * B_MAT + rr * B_STRIDE + seg * 16;
                const __nv_bfloat16* src = (mat ? g_cl : g_ch)
                    + ((size_t)(chunk * BN + rr) * DDIM + seg * 8);
                cp16(dst, src);
            }
            CP_COMMIT();
        }

        for (int ks = 0; ks < 4; ks++) {
            if (ks < 3) {
                int nb = (ks + 1) & 1;
                #pragma unroll
                for (int i = 0; i < 8; i++) {
                    int linear = tid + i * 256;
                    int mat = linear >> 10, rr = (linear >> 3) & 127, seg = linear & 7;
                    uint32_t dst = sb + SM_B + nb * B_STAGE + mat * B_MAT
                                 + rr * B_STRIDE + seg * 16;
                    const __nv_bfloat16* src = (mat ? g_cl : g_ch)
                        + ((size_t)(chunk * BN + rr) * DDIM + (ks + 1) * 64 + seg * 8);
                    cp16(dst, src);
                }
                CP_COMMIT();
                CP_WAIT(1);
            } else {
                CP_WAIT(0);
            }
            __syncthreads();

            const uint32_t bbase = sb + SM_B + (ks & 1) * B_STAGE;
            #pragma unroll
            for (int k16 = 0; k16 < 4; k16++) {
                int kel = k16 * 16;
                uint32_t ah[4][4], al[4][4];
                #pragma unroll
                for (int mt = 0; mt < 4; mt++) {
                    uint32_t ar = sb + SM_A_H
                        + (wm * 64 + mt * 16 + (lane & 15)) * A_STRIDE
                        + (ks * 64 + kel + (lane >> 4) * 8) * 2;
                    ldsm4(ah[mt], ar);
                    ldsm4(al[mt], ar + (SM_A_L - SM_A_H));
                }
                #pragma unroll
                for (int np = 0; np < 2; np++) {
                    uint32_t bh[4], bl[4];
                    uint32_t br = bbase
                        + (wn * 32 + np * 16 + (lane & 7) + (lane >> 4) * 8) * B_STRIDE
                        + (kel + ((lane >> 3) & 1) * 8) * 2;
                    ldsm4(bh, br);
                    ldsm4(bl, br + B_MAT);
                    #pragma unroll
                    for (int mt = 0; mt < 4; mt++) {
                        mma_bf16(acc[mt][np * 2 + 0], ah[mt], bh + 0);
                        mma_bf16(acc[mt][np * 2 + 1], ah[mt], bh + 2);
                        mma_bf16(acc[mt][np * 2 + 0], ah[mt], bl + 0);
                        mma_bf16(acc[mt][np * 2 + 1], ah[mt], bl + 2);
                        mma_bf16(acc[mt][np * 2 + 0], al[mt], bh + 0);
                        mma_bf16(acc[mt][np * 2 + 1], al[mt], bh + 2);
                    }
                }
            }
            __syncthreads();
        }

        #pragma unroll
        for (int mt = 0; mt < 4; mt++) {
            #pragma unroll
            for (int nt = 0; nt < 4; nt++) {
                int col = chunk * BN + wn * 32 + nt * 8 + (lane & 3) * 2;
                float s0 = cn_s[col]     - 2.0f * acc[mt][nt][0];
                float s1 = cn_s[col + 1] - 2.0f * acc[mt][nt][1];
                float s2 = cn_s[col]     - 2.0f * acc[mt][nt][2];
                float s3 = cn_s[col + 1] - 2.0f * acc[mt][nt][3];
                int sl0 = mt * 2, sl1 = mt * 2 + 1;
                if (s0 < bv[sl0]) { b2[sl0] = bv[sl0]; bv[sl0] = s0; bi[sl0] = col; }
                else b2[sl0] = fminf(b2[sl0], s0);
                if (s1 < bv[sl0]) { b2[sl0] = bv[sl0]; bv[sl0] = s1; bi[sl0] = col + 1; }
                else b2[sl0] = fminf(b2[sl0], s1);
                if (s2 < bv[sl1]) { b2[sl1] = bv[sl1]; bv[sl1] = s2; bi[sl1] = col; }
                else b2[sl1] = fminf(b2[sl1], s2);
                if (s3 < bv[sl1]) { b2[sl1] = bv[sl1]; bv[sl1] = s3; bi[sl1] = col + 1; }
                else b2[sl1] = fminf(b2[sl1], s3);
            }
        }
    }

    #pragma unroll
    for (int s = 0; s < 8; s++) {
        #pragma unroll
        for (int off = 1; off <= 2; off <<= 1) {
            float ov = __shfl_xor_sync(0xffffffffu, bv[s], off);
            float o2 = __shfl_xor_sync(0xffffffffu, b2[s], off);
            int   oi = __shfl_xor_sync(0xffffffffu, bi[s], off);
            float n2 = fminf(fminf(b2[s], o2), fmaxf(bv[s], ov));
            if (ov < bv[s] || (ov == bv[s] && oi < bi[s])) { bv[s] = ov; bi[s] = oi; }
            b2[s] = n2;
        }
    }
    __syncthreads();

    float* V1 = (float*)(smem + SM_B);
    float* V2 = (float*)(smem + SM_B + 2048);
    int*   I1 = (int*)(smem + SM_B + 4096);
    if ((lane & 3) == 0) {
        #pragma unroll
        for (int s = 0; s < 8; s++) {
            int mt = s >> 1, hi = s & 1;
            int r = wm * 64 + mt * 16 + (lane >> 2) + hi * 8;
            V1[r * 4 + wn] = bv[s];
            V2[r * 4 + wn] = b2[s];
            I1[r * 4 + wn] = bi[s];
        }
    }
    __syncthreads();

    const long long NQ = (long long)nrows * DDIM;
    if (tid < BM) {
        float v1 = V1[tid * 4], v2 = V2[tid * 4];
        int   i1 = I1[tid * 4];
        #pragma unroll
        for (int j = 1; j < 4; j++) {
            float a1 = V1[tid * 4 + j], a2 = V2[tid * 4 + j];
            int   ai = I1[tid * 4 + j];
            float n2 = fminf(fminf(v2, a2), fmaxf(v1, a1));
            if (a1 < v1 || (a1 == v1 && ai < i1)) { v1 = a1; i1 = ai; }
            v2 = n2;
        }
        bidx_s[tid] = i1;
        long long row = row_base + tid;
        if (v2 - v1 < MARGIN) {
            int slot = atomicAdd(&g_cnt, 1);
            g_list[slot] = (int)row;
        }
        if (out_size >= NQ + nrows) out[NQ + row] = (float)i1;
        else if (out_size < NQ && row < out_size) out[row] = (float)i1;
    }
    __syncthreads();

    if (out_size >= NQ) {
        const float4* c4 = (const float4*)codes;
        float4* o4 = (float4*)out;
        for (int i = tid; i < BM * (DDIM / 4); i += 256) {
            int r = i >> 6;
            int q = i & 63;
            o4[(size_t)(row_base + r) * (DDIM / 4) + q] =
                c4[(size_t)bidx_s[r] * (DDIM / 4) + q];
        }
    }
}

// ---------------------------------------------------------------------------
// Refine kernel v2: fp32 prefilter, then exact fp64 + tie window only for
// candidates within FILT_EPS of the fp32 min. Decision logic on survivors is
// identical to the R5/R7 passing version.
// ---------------------------------------------------------------------------
__global__ void __launch_bounds__(256)
refine_kernel(const float* __restrict__ x, const float* __restrict__ codes,
              float* __restrict__ out, long long NQ, long long out_size,
              int nrows, int C)
{
    __shared__ float  xr[DDIM];
    __shared__ double partial[256];
    __shared__ float  fv[256];
    __shared__ int    fi[256];
    __shared__ int    sel;
    __shared__ float  vm_s;

    int t = threadIdx.x;
    int cnt = g_cnt;
    if (cnt > 65536) cnt = 65536;

    for (int w = blockIdx.x; w < cnt; w += gridDim.x) {
        int row = g_list[w];
        xr[t] = x[(size_t)row * DDIM + t];
        __syncthreads();

        // s1 = ||x||^2 correctly rounded
        partial[t] = (double)xr[t] * (double)xr[t];
        __syncthreads();
        for (int s = 128; s; s >>= 1) {
            if (t < s) partial[t] += partial[t + s];
            __syncthreads();
        }
        float s1f = (float)partial[0];

        // --- pass 1: cheap fp32 scores (independent chains) ---
        float dv[4];
        #pragma unroll
        for (int c4i = 0; c4i < 4; c4i++) {
            int c = t + 256 * c4i;
            dv[c4i] = 3.4e38f;
            if (c < C) {
                const float* crow = codes + (size_t)c * DDIM;
                float d0 = 0.f, d1 = 0.f, d2 = 0.f, d3 = 0.f;
                #pragma unroll 4
                for (int k = 0; k < DDIM; k += 4) {
                    d0 = fmaf(xr[k],     __ldg(&crow[k]),     d0);
                    d1 = fmaf(xr[k + 1], __ldg(&crow[k + 1]), d1);
                    d2 = fmaf(xr[k + 2], __ldg(&crow[k + 2]), d2);
                    d3 = fmaf(xr[k + 3], __ldg(&crow[k + 3]), d3);
                }
                float dot = (d0 + d1) + (d2 + d3);
                dv[c4i] = (s1f - 2.0f * dot) + g_cnorm[c];
            }
        }
        float bvv = fminf(fminf(dv[0], dv[1]), fminf(dv[2], dv[3]));
        fv[t] = bvv;
        __syncthreads();
        for (int s = 128; s; s >>= 1) {
            if (t < s) fv[t] = fminf(fv[t], fv[t + s]);
            __syncthreads();
        }
        float filt = fv[0] + FILT_EPS;
        __syncthreads();

        // --- pass 2: exact fp64 -> d32 for surviving candidates only ---
        float ev[4];
        #pragma unroll
        for (int c4i = 0; c4i < 4; c4i++) {
            int c = t + 256 * c4i;
            ev[c4i] = 3.4e38f;
            if (c < C && dv[c4i] <= filt) {
                const float* crow = codes + (size_t)c * DDIM;
                double dot = 0.0;
                #pragma unroll 8
                for (int k = 0; k < DDIM; k++)
                    dot = fma((double)xr[k], (double)__ldg(&crow[k]), dot);
                float dotf = (float)dot;
                float t1   = s1f - 2.0f * dotf;
                ev[c4i]    = t1 + g_cnorm[c];
            }
        }

        float bvx = fminf(fminf(ev[0], ev[1]), fminf(ev[2], ev[3]));
        fv[t] = bvx;
        __syncthreads();
        for (int s = 128; s; s >>= 1) {
            if (t < s) fv[t] = fminf(fv[t], fv[t + s]);
            __syncthreads();
        }
        if (t == 0) vm_s = fv[0];
        __syncthreads();
        float vm = vm_s;
        float tie_hi = __int_as_float(__float_as_int(vm) + TIE_ULPS);

        int bii = 0x7fffffff;
        #pragma unroll
        for (int c4i = 0; c4i < 4; c4i++) {
            int c = t + 256 * c4i;
            if (c < C && ev[c4i] <= tie_hi && c < bii) bii = c;
        }
        fi[t] = bii;
        __syncthreads();
        for (int s = 128; s; s >>= 1) {
            if (t < s) fi[t] = min(fi[t], fi[t + s]);
            __syncthreads();
        }
        if (t == 0) {
            sel = fi[0];
            if (out_size >= NQ + nrows) out[NQ + row] = (float)fi[0];
            else if (out_size < NQ && row < out_size) out[row] = (float)fi[0];
        }
        __syncthreads();

        if (out_size >= NQ)
            out[(size_t)row * DDIM + t] = codes[(size_t)sel * DDIM + t];
        __syncthreads();
    }
}

// ---------------------------------------------------------------------------
extern "C" void kernel_launch(void* const* d_in, const int* in_sizes, int n_in,
                              void* d_out, int out_size)
{
    const float* x     = (const float*)d_in[0];
    const float* codes = (const float*)d_in[1];
    int nrows = in_sizes[0] / DDIM;   // 65536
    int C     = in_sizes[1] / DDIM;   // 1024

    cudaFuncSetAttribute(vq_mma, cudaFuncAttributeMaxDynamicSharedMemorySize,
                         SM_TOTAL);

    reset_kernel<<<1, 1>>>();
    prep_codes<<<C, 256>>>(codes);

    vq_mma<<<nrows / BM, 256, SM_TOTAL>>>(x, codes, (float*)d_out,
                                          (long long)out_size, nrows);

    long long NQ = (long long)nrows * DDIM;
    refine_kernel<<<512, 256>>>(x, codes, (float*)d_out, NQ,
                                (long long)out_size, nrows, C);
}

// round 9
// speedup vs baseline: 7.8843x; 1.4569x over previous
#include <cuda_runtime.h>
#include <cuda_bf16.h>
#include <cstdint>

// Problem constants (fixed by dataset)
#define DDIM 256
#define CODES 1024
#define BM   128          // rows per CTA
#define BN   128          // codes per chunk
#define NCHUNK 8
#define MARGIN 4e-3f
#define TIE_ULPS 2
#define FILT_EPS 4e-3f

// dynamic smem layout (bytes)
#define SM_CN     0          // 1024 f32          (4096)
#define SM_BIDX   4096       // 128 int           (512)
#define SM_A_H    8192       // 128 rows x 528B   (67584)
#define SM_A_L    75776      // 128 rows x 528B   (67584)
#define SM_B      143360     // 2 stages x 2 mats x 128 x 144B (73728)
#define SM_TOTAL  217088
#define A_STRIDE  528        // 256 bf16 + 8 pad elems
#define B_STRIDE  144        // 64 bf16 + 8 pad elems
#define B_MAT     18432      // 128 * 144
#define B_STAGE   36864      // 2 matrices

__device__ float                          g_cnorm[1024];
__device__ __align__(256) __nv_bfloat16   g_ch[1024 * 256];
__device__ __align__(256) __nv_bfloat16   g_cl[1024 * 256];
__device__ int                            g_list[65536];
__device__ int                            g_cnt;

// ---------------------------------------------------------------------------
__device__ __forceinline__ uint32_t smem_to_u32(const void* p) {
    uint32_t a;
    asm("{ .reg .u64 t; cvta.to.shared.u64 t, %1; cvt.u32.u64 %0, t; }"
        : "=r"(a) : "l"(p));
    return a;
}
__device__ __forceinline__ void cp16(uint32_t dst, const void* src) {
    asm volatile("cp.async.cg.shared.global [%0], [%1], 16;"
                 :: "r"(dst), "l"(src));
}
#define CP_COMMIT() asm volatile("cp.async.commit_group;" ::: "memory")
#define CP_WAIT(n)  asm volatile("cp.async.wait_group %0;" :: "n"(n) : "memory")

__device__ __forceinline__ void ldsm4(uint32_t* r, uint32_t addr) {
    asm volatile("ldmatrix.sync.aligned.m8n8.x4.shared.b16 {%0,%1,%2,%3}, [%4];"
                 : "=r"(r[0]), "=r"(r[1]), "=r"(r[2]), "=r"(r[3]) : "r"(addr));
}
__device__ __forceinline__ void mma_bf16(float* d, const uint32_t* a,
                                         const uint32_t* b) {
    asm volatile(
        "mma.sync.aligned.m16n8k16.row.col.f32.bf16.bf16.f32 "
        "{%0,%1,%2,%3}, {%4,%5,%6,%7}, {%8,%9}, {%0,%1,%2,%3};"
        : "+f"(d[0]), "+f"(d[1]), "+f"(d[2]), "+f"(d[3])
        : "r"(a[0]), "r"(a[1]), "r"(a[2]), "r"(a[3]), "r"(b[0]), "r"(b[1]));
}

// ---------------------------------------------------------------------------
__global__ void reset_kernel() { g_cnt = 0; }

// Merged prep: bf16 hi/lo split + ||c||^2 (fp64 -> fp32). One block per code.
__global__ void prep_codes(const float* __restrict__ codes) {
    __shared__ double partial[256];
    int c = blockIdx.x;
    int t = threadIdx.x;
    float v = codes[(size_t)c * DDIM + t];
    __nv_bfloat16 h = __float2bfloat16_rn(v);
    float lo = v - __bfloat162float(h);
    g_ch[(size_t)c * DDIM + t] = h;
    g_cl[(size_t)c * DDIM + t] = __float2bfloat16_rn(lo);
    partial[t] = (double)v * (double)v;
    __syncthreads();
    for (int s = 128; s; s >>= 1) {
        if (t < s) partial[t] += partial[t + s];
        __syncthreads();
    }
    if (t == 0) g_cnorm[c] = (float)partial[0];
}

// ---------------------------------------------------------------------------
// HMMA ranking kernel: dot = xh.ch + xh.cl + xl.ch (bf16 in, fp32 acc)
// (mainloop identical to R7/R8 pass; only MARGIN changed)
// ---------------------------------------------------------------------------
__global__ void __launch_bounds__(256, 1)
vq_mma(const float* __restrict__ x, const float* __restrict__ codes,
       float* __restrict__ out, long long out_size, int nrows)
{
    extern __shared__ char smem[];
    const uint32_t sb   = smem_to_u32(smem);
    const int tid  = threadIdx.x;
    const int wid  = tid >> 5;
    const int lane = tid & 31;
    const int wm   = wid & 1;
    const int wn   = wid >> 1;
    const int row_base = blockIdx.x * BM;

    float* cn_s   = (float*)(smem + SM_CN);
    int*   bidx_s = (int*)(smem + SM_BIDX);

    for (int i = tid; i < CODES; i += 256) cn_s[i] = g_cnorm[i];

    const float4* x4 = (const float4*)x + (size_t)row_base * (DDIM / 4);
    for (int idx = tid; idx < BM * (DDIM / 4); idx += 256) {
        float4 v = x4[idx];
        int r  = idx >> 6;
        int kq = idx & 63;
        __nv_bfloat16 h0 = __float2bfloat16_rn(v.x);
        __nv_bfloat16 h1 = __float2bfloat16_rn(v.y);
        __nv_bfloat16 h2 = __float2bfloat16_rn(v.z);
        __nv_bfloat16 h3 = __float2bfloat16_rn(v.w);
        __nv_bfloat16 l0 = __float2bfloat16_rn(v.x - __bfloat162float(h0));
        __nv_bfloat16 l1 = __float2bfloat16_rn(v.y - __bfloat162float(h1));
        __nv_bfloat16 l2 = __float2bfloat16_rn(v.z - __bfloat162float(h2));
        __nv_bfloat16 l3 = __float2bfloat16_rn(v.w - __bfloat162float(h3));
        uint32_t h01 = ((uint32_t)__bfloat16_as_ushort(h1) << 16) | __bfloat16_as_ushort(h0);
        uint32_t h23 = ((uint32_t)__bfloat16_as_ushort(h3) << 16) | __bfloat16_as_ushort(h2);
        uint32_t l01 = ((uint32_t)__bfloat16_as_ushort(l1) << 16) | __bfloat16_as_ushort(l0);
        uint32_t l23 = ((uint32_t)__bfloat16_as_ushort(l3) << 16) | __bfloat16_as_ushort(l2);
        int off = r * A_STRIDE + kq * 8;
        *(uint32_t*)(smem + SM_A_H + off)     = h01;
        *(uint32_t*)(smem + SM_A_H + off + 4) = h23;
        *(uint32_t*)(smem + SM_A_L + off)     = l01;
        *(uint32_t*)(smem + SM_A_L + off + 4) = l23;
    }
    __syncthreads();

    float bv[8], b2[8];
    int   bi[8];
    #pragma unroll
    for (int i = 0; i < 8; i++) { bv[i] = 3.4e38f; b2[i] = 3.4e38f; bi[i] = 0; }

    for (int chunk = 0; chunk < NCHUNK; chunk++) {
        float acc[4][4][4];
        #pragma unroll
        for (int m = 0; m < 4; m++)
            #pragma unroll
            for (int n = 0; n < 4; n++)
                #pragma unroll
                for (int q = 0; q < 4; q++) acc[m][n][q] = 0.0f;

        {
            #pragma unroll
            for (int i = 0; i < 8; i++) {
                int linear = tid + i * 256;
                int mat = linear >> 10, rr = (linear >> 3) & 127, seg = linear & 7;
                uint32_t dst = sb + SM_B + mat * B_MAT + rr * B_STRIDE + seg * 16;
                const __nv_bfloat16* src = (mat ? g_cl : g_ch)
                    + ((size_t)(chunk * BN + rr) * DDIM + seg * 8);
                cp16(dst, src);
            }
            CP_COMMIT();
        }

        for (int ks = 0; ks < 4; ks++) {
            if (ks < 3) {
                int nb = (ks + 1) & 1;
                #pragma unroll
                for (int i = 0; i < 8; i++) {
                    int linear = tid + i * 256;
                    int mat = linear >> 10, rr = (linear >> 3) & 127, seg = linear & 7;
                    uint32_t dst = sb + SM_B + nb * B_STAGE + mat * B_MAT
                                 + rr * B_STRIDE + seg * 16;
                    const __nv_bfloat16* src = (mat ? g_cl : g_ch)
                        + ((size_t)(chunk * BN + rr) * DDIM + (ks + 1) * 64 + seg * 8);
                    cp16(dst, src);
                }
                CP_COMMIT();
                CP_WAIT(1);
            } else {
                CP_WAIT(0);
            }
            __syncthreads();

            const uint32_t bbase = sb + SM_B + (ks & 1) * B_STAGE;
            #pragma unroll
            for (int k16 = 0; k16 < 4; k16++) {
                int kel = k16 * 16;
                uint32_t ah[4][4], al[4][4];
                #pragma unroll
                for (int mt = 0; mt < 4; mt++) {
                    uint32_t ar = sb + SM_A_H
                        + (wm * 64 + mt * 16 + (lane & 15)) * A_STRIDE
                        + (ks * 64 + kel + (lane >> 4) * 8) * 2;
                    ldsm4(ah[mt], ar);
                    ldsm4(al[mt], ar + (SM_A_L - SM_A_H));
                }
                #pragma unroll
                for (int np = 0; np < 2; np++) {
                    uint32_t bh[4], bl[4];
                    uint32_t br = bbase
                        + (wn * 32 + np * 16 + (lane & 7) + (lane >> 4) * 8) * B_STRIDE
                        + (kel + ((lane >> 3) & 1) * 8) * 2;
                    ldsm4(bh, br);
                    ldsm4(bl, br + B_MAT);
                    #pragma unroll
                    for (int mt = 0; mt < 4; mt++) {
                        mma_bf16(acc[mt][np * 2 + 0], ah[mt], bh + 0);
                        mma_bf16(acc[mt][np * 2 + 1], ah[mt], bh + 2);
                        mma_bf16(acc[mt][np * 2 + 0], ah[mt], bl + 0);
                        mma_bf16(acc[mt][np * 2 + 1], ah[mt], bl + 2);
                        mma_bf16(acc[mt][np * 2 + 0], al[mt], bh + 0);
                        mma_bf16(acc[mt][np * 2 + 1], al[mt], bh + 2);
                    }
                }
            }
            __syncthreads();
        }

        #pragma unroll
        for (int mt = 0; mt < 4; mt++) {
            #pragma unroll
            for (int nt = 0; nt < 4; nt++) {
                int col = chunk * BN + wn * 32 + nt * 8 + (lane & 3) * 2;
                float s0 = cn_s[col]     - 2.0f * acc[mt][nt][0];
                float s1 = cn_s[col + 1] - 2.0f * acc[mt][nt][1];
                float s2 = cn_s[col]     - 2.0f * acc[mt][nt][2];
                float s3 = cn_s[col + 1] - 2.0f * acc[mt][nt][3];
                int sl0 = mt * 2, sl1 = mt * 2 + 1;
                if (s0 < bv[sl0]) { b2[sl0] = bv[sl0]; bv[sl0] = s0; bi[sl0] = col; }
                else b2[sl0] = fminf(b2[sl0], s0);
                if (s1 < bv[sl0]) { b2[sl0] = bv[sl0]; bv[sl0] = s1; bi[sl0] = col + 1; }
                else b2[sl0] = fminf(b2[sl0], s1);
                if (s2 < bv[sl1]) { b2[sl1] = bv[sl1]; bv[sl1] = s2; bi[sl1] = col; }
                else b2[sl1] = fminf(b2[sl1], s2);
                if (s3 < bv[sl1]) { b2[sl1] = bv[sl1]; bv[sl1] = s3; bi[sl1] = col + 1; }
                else b2[sl1] = fminf(b2[sl1], s3);
            }
        }
    }

    #pragma unroll
    for (int s = 0; s < 8; s++) {
        #pragma unroll
        for (int off = 1; off <= 2; off <<= 1) {
            float ov = __shfl_xor_sync(0xffffffffu, bv[s], off);
            float o2 = __shfl_xor_sync(0xffffffffu, b2[s], off);
            int   oi = __shfl_xor_sync(0xffffffffu, bi[s], off);
            float n2 = fminf(fminf(b2[s], o2), fmaxf(bv[s], ov));
            if (ov < bv[s] || (ov == bv[s] && oi < bi[s])) { bv[s] = ov; bi[s] = oi; }
            b2[s] = n2;
        }
    }
    __syncthreads();

    float* V1 = (float*)(smem + SM_B);
    float* V2 = (float*)(smem + SM_B + 2048);
    int*   I1 = (int*)(smem + SM_B + 4096);
    if ((lane & 3) == 0) {
        #pragma unroll
        for (int s = 0; s < 8; s++) {
            int mt = s >> 1, hi = s & 1;
            int r = wm * 64 + mt * 16 + (lane >> 2) + hi * 8;
            V1[r * 4 + wn] = bv[s];
            V2[r * 4 + wn] = b2[s];
            I1[r * 4 + wn] = bi[s];
        }
    }
    __syncthreads();

    const long long NQ = (long long)nrows * DDIM;
    if (tid < BM) {
        float v1 = V1[tid * 4], v2 = V2[tid * 4];
        int   i1 = I1[tid * 4];
        #pragma unroll
        for (int j = 1; j < 4; j++) {
            float a1 = V1[tid * 4 + j], a2 = V2[tid * 4 + j];
            int   ai = I1[tid * 4 + j];
            float n2 = fminf(fminf(v2, a2), fmaxf(v1, a1));
            if (a1 < v1 || (a1 == v1 && ai < i1)) { v1 = a1; i1 = ai; }
            v2 = n2;
        }
        bidx_s[tid] = i1;
        long long row = row_base + tid;
        if (v2 - v1 < MARGIN) {
            int slot = atomicAdd(&g_cnt, 1);
            g_list[slot] = (int)row;
        }
        if (out_size >= NQ + nrows) out[NQ + row] = (float)i1;
        else if (out_size < NQ && row < out_size) out[row] = (float)i1;
    }
    __syncthreads();

    if (out_size >= NQ) {
        const float4* c4 = (const float4*)codes;
        float4* o4 = (float4*)out;
        for (int i = tid; i < BM * (DDIM / 4); i += 256) {
            int r = i >> 6;
            int q = i & 63;
            o4[(size_t)(row_base + r) * (DDIM / 4) + q] =
                c4[(size_t)bidx_s[r] * (DDIM / 4) + q];
        }
    }
}

// ---------------------------------------------------------------------------
// Refine kernel v3: pass1 with float4 loads + 16 interleaved FMA chains,
// then exact fp64 + tie window only for candidates within FILT_EPS of the
// fp32 min. Survivor decision logic identical to R5/R7/R8 passing versions.
// ---------------------------------------------------------------------------
__global__ void __launch_bounds__(256)
refine_kernel(const float* __restrict__ x, const float* __restrict__ codes,
              float* __restrict__ out, long long NQ, long long out_size,
              int nrows, int C)
{
    __shared__ __align__(16) float xr[DDIM];
    __shared__ double partial[256];
    __shared__ float  fv[256];
    __shared__ int    fi[256];
    __shared__ int    sel;
    __shared__ float  vm_s;

    int t = threadIdx.x;
    int cnt = g_cnt;
    if (cnt > 65536) cnt = 65536;

    for (int w = blockIdx.x; w < cnt; w += gridDim.x) {
        int row = g_list[w];
        xr[t] = x[(size_t)row * DDIM + t];
        __syncthreads();

        // s1 = ||x||^2 correctly rounded
        partial[t] = (double)xr[t] * (double)xr[t];
        __syncthreads();
        for (int s = 128; s; s >>= 1) {
            if (t < s) partial[t] += partial[t + s];
            __syncthreads();
        }
        float s1f = (float)partial[0];

        // --- pass 1: fp32 scores via float4, 16 interleaved chains ---
        const float4* xr4 = (const float4*)xr;
        const float4* crow4[4];
        #pragma unroll
        for (int c4i = 0; c4i < 4; c4i++)
            crow4[c4i] = (const float4*)(codes + (size_t)(t + 256 * c4i) * DDIM);

        float4 accv[4];
        #pragma unroll
        for (int c4i = 0; c4i < 4; c4i++)
            accv[c4i] = make_float4(0.f, 0.f, 0.f, 0.f);

        #pragma unroll 4
        for (int k4 = 0; k4 < DDIM / 4; k4++) {
            float4 xv = xr4[k4];
            #pragma unroll
            for (int c4i = 0; c4i < 4; c4i++) {
                float4 cv = __ldg(&crow4[c4i][k4]);
                accv[c4i].x = fmaf(xv.x, cv.x, accv[c4i].x);
                accv[c4i].y = fmaf(xv.y, cv.y, accv[c4i].y);
                accv[c4i].z = fmaf(xv.z, cv.z, accv[c4i].z);
                accv[c4i].w = fmaf(xv.w, cv.w, accv[c4i].w);
            }
        }

        float dv[4];
        #pragma unroll
        for (int c4i = 0; c4i < 4; c4i++) {
            float dot = (accv[c4i].x + accv[c4i].y) + (accv[c4i].z + accv[c4i].w);
            dv[c4i] = (s1f - 2.0f * dot) + g_cnorm[t + 256 * c4i];
        }

        float bvv = fminf(fminf(dv[0], dv[1]), fminf(dv[2], dv[3]));
        fv[t] = bvv;
        __syncthreads();
        for (int s = 128; s; s >>= 1) {
            if (t < s) fv[t] = fminf(fv[t], fv[t + s]);
            __syncthreads();
        }
        float filt = fv[0] + FILT_EPS;
        __syncthreads();

        // --- pass 2: exact fp64 -> d32 for surviving candidates only ---
        float ev[4];
        #pragma unroll
        for (int c4i = 0; c4i < 4; c4i++) {
            int c = t + 256 * c4i;
            ev[c4i] = 3.4e38f;
            if (dv[c4i] <= filt) {
                const float* crow = codes + (size_t)c * DDIM;
                double dot = 0.0;
                #pragma unroll 8
                for (int k = 0; k < DDIM; k++)
                    dot = fma((double)xr[k], (double)__ldg(&crow[k]), dot);
                float dotf = (float)dot;
                float t1   = s1f - 2.0f * dotf;
                ev[c4i]    = t1 + g_cnorm[c];
            }
        }

        float bvx = fminf(fminf(ev[0], ev[1]), fminf(ev[2], ev[3]));
        fv[t] = bvx;
        __syncthreads();
        for (int s = 128; s; s >>= 1) {
            if (t < s) fv[t] = fminf(fv[t], fv[t + s]);
            __syncthreads();
        }
        if (t == 0) vm_s = fv[0];
        __syncthreads();
        float vm = vm_s;
        float tie_hi = __int_as_float(__float_as_int(vm) + TIE_ULPS);

        int bii = 0x7fffffff;
        #pragma unroll
        for (int c4i = 0; c4i < 4; c4i++) {
            int c = t + 256 * c4i;
            if (ev[c4i] <= tie_hi && c < bii) bii = c;
        }
        fi[t] = bii;
        __syncthreads();
        for (int s = 128; s; s >>= 1) {
            if (t < s) fi[t] = min(fi[t], fi[t + s]);
            __syncthreads();
        }
        if (t == 0) {
            sel = fi[0];
            if (out_size >= NQ + nrows) out[NQ + row] = (float)fi[0];
            else if (out_size < NQ && row < out_size) out[row] = (float)fi[0];
        }
        __syncthreads();

        if (out_size >= NQ)
            out[(size_t)row * DDIM + t] = codes[(size_t)sel * DDIM + t];
        __syncthreads();
    }
}

// ---------------------------------------------------------------------------
extern "C" void kernel_launch(void* const* d_in, const int* in_sizes, int n_in,
                              void* d_out, int out_size)
{
    const float* x     = (const float*)d_in[0];
    const float* codes = (const float*)d_in[1];
    int nrows = in_sizes[0] / DDIM;   // 65536
    int C     = in_sizes[1] / DDIM;   // 1024

    cudaFuncSetAttribute(vq_mma, cudaFuncAttributeMaxDynamicSharedMemorySize,
                         SM_TOTAL);

    reset_kernel<<<1, 1>>>();
    prep_codes<<<C, 256>>>(codes);

    vq_mma<<<nrows / BM, 256, SM_TOTAL>>>(x, codes, (float*)d_out,
                                          (long long)out_size, nrows);

    long long NQ = (long long)nrows * DDIM;
    refine_kernel<<<512, 256>>>(x, codes, (float*)d_out, NQ,
                                (long long)out_size, nrows, C);
}